// round 2
// baseline (speedup 1.0000x reference)
#include <cuda_runtime.h>
#include <cstdint>

#define N_ANCH   300000
#define N_CLS    80
#define DET_DIM  85
#define TOPK     1000
#define MAXBOX   300
#define CAP      4096
#define NMS_THR  0.4f

#define ABLK     80          // anchors per block in score kernel
#define ATHREADS 320         // threads per block in score kernel
#define AGRID    (N_ANCH / ABLK)   // 3750

// ---------------- device scratch ----------------
__device__ unsigned int g_scores[N_ANCH];
__device__ unsigned int g_hist1[65536];   // bits [31:16]; zeroed by resolve1 after use
__device__ unsigned int g_hist2[256];     // bits [15:8] within winning bucket; zeroed by score kernel
__device__ unsigned int g_sel_b;          // winning 16-bit bucket
__device__ unsigned int g_kth2;           // remaining k within bucket
__device__ int          g_topk_idx[TOPK];
__device__ float4       g_boxk[TOPK];
__device__ unsigned int g_maskmat[TOPK * 32];

// ========== 1. coalesced per-anchor max + 16-bit histogram ==========
__global__ void score_hist_kernel(const float* __restrict__ cls) {
    __shared__ unsigned int smax[ABLK];
    int t = threadIdx.x;
    if (t < ABLK) smax[t] = 0u;
    if (blockIdx.x == 0 && t < 256) g_hist2[t] = 0u;   // prep for hist2 this replay
    __syncthreads();

    const float4* p = (const float4*)cls;
    size_t base = (size_t)blockIdx.x * (ABLK * N_CLS / 4);   // float4 units
#pragma unroll
    for (int j = 0; j < 5; j++) {
        int off = t + j * ATHREADS;                 // 0..1599
        float4 v = p[base + off];
        float m = fmaxf(fmaxf(v.x, v.y), fmaxf(v.z, v.w));
        atomicMax(&smax[off / (N_CLS / 4)], __float_as_uint(m));   // scores >= 0
    }
    __syncthreads();

    if (t < ABLK) {
        unsigned int k = smax[t];
        g_scores[blockIdx.x * ABLK + t] = k;
        unsigned int bucket = k >> 16;
        // warp-aggregated global atomic (top bucket is very hot)
        unsigned int amask = __activemask();
        unsigned int peers = __match_any_sync(amask, bucket);
        int leader = __ffs(peers) - 1;
        if ((t & 31) == leader) atomicAdd(&g_hist1[bucket], __popc(peers));
    }
}

// ========== 2. resolve round 1: winning 16-bit bucket (+ zero hist1) ==========
__global__ void resolve1_kernel() {
    __shared__ unsigned int suf[1024];
    __shared__ unsigned int win64[64];
    __shared__ int s_win;
    int t = threadIdx.x;   // 1024

    // per-thread sum of its 64 contiguous counters
    unsigned int s = 0;
    const uint4* hp = (const uint4*)g_hist1;
#pragma unroll
    for (int i = 0; i < 16; i++) {
        uint4 v = hp[t * 16 + i];
        s += v.x + v.y + v.z + v.w;
    }
    suf[t] = s;
    __syncthreads();
    // inclusive suffix scan over 1024
    for (int off = 1; off < 1024; off <<= 1) {
        unsigned int v = suf[t];
        unsigned int u = (t + off < 1024) ? suf[t + off] : 0u;
        __syncthreads();
        suf[t] = v + u;
        __syncthreads();
    }
    unsigned int excl = (t < 1023) ? suf[t + 1] : 0u;
    if (excl < TOPK && suf[t] >= TOPK) s_win = t;
    __syncthreads();

    int w = s_win;
    unsigned int wexcl = (w < 1023) ? suf[w + 1] : 0u;   // count strictly above w's range
    if (t < 64) win64[t] = g_hist1[w * 64 + t];
    __syncthreads();
    // suffix scan over the 64 winner counters
    for (int off = 1; off < 64; off <<= 1) {
        unsigned int v = 0, u = 0;
        if (t < 64) { v = win64[t]; u = (t + off < 64) ? win64[t + off] : 0u; }
        __syncthreads();
        if (t < 64) win64[t] = v + u;
        __syncthreads();
    }
    if (t < 64) {
        unsigned int e = wexcl + ((t < 63) ? win64[t + 1] : 0u);   // count above bucket (w*64+t)
        unsigned int inc = wexcl + win64[t];
        if (e < TOPK && inc >= TOPK) {
            g_sel_b = (unsigned int)(w * 64 + t);
            g_kth2  = TOPK - e;
        }
    }
    __syncthreads();
    // zero hist1 for next replay
    uint4 z = make_uint4(0, 0, 0, 0);
    uint4* hz = (uint4*)g_hist1;
#pragma unroll
    for (int i = 0; i < 16; i++) hz[t * 16 + i] = z;
}

// ========== 3. 8-bit refinement histogram within winning bucket ==========
__global__ void hist2_kernel() {
    unsigned int b = g_sel_b;
    int i = blockIdx.x * blockDim.x + threadIdx.x;
    if (i >= N_ANCH / 4) return;
    uint4 k = ((const uint4*)g_scores)[i];
    if ((k.x >> 16) == b) atomicAdd(&g_hist2[(k.x >> 8) & 255u], 1u);
    if ((k.y >> 16) == b) atomicAdd(&g_hist2[(k.y >> 8) & 255u], 1u);
    if ((k.z >> 16) == b) atomicAdd(&g_hist2[(k.z >> 8) & 255u], 1u);
    if ((k.w >> 16) == b) atomicAdd(&g_hist2[(k.w >> 8) & 255u], 1u);
}

// ========== 4. resolve2 + compact + bitonic sort + box gather (one block) ==========
__global__ void select_sort_kernel(const float* __restrict__ boxes) {
    __shared__ unsigned long long cand[CAP];
    __shared__ unsigned int h2[256];
    __shared__ unsigned int s_T;
    __shared__ int s_cnt;
    int t = threadIdx.x;   // 1024

    if (t == 0) s_cnt = 0;
    if (t < 256) h2[t] = g_hist2[t];
    __syncthreads();
    // suffix scan over 256
    for (int off = 1; off < 256; off <<= 1) {
        unsigned int v = 0, u = 0;
        if (t < 256) { v = h2[t]; u = (t + off < 256) ? h2[t + off] : 0u; }
        __syncthreads();
        if (t < 256) h2[t] = v + u;
        __syncthreads();
    }
    if (t < 256) {
        unsigned int kth = g_kth2;
        unsigned int e = (t < 255) ? h2[t + 1] : 0u;
        if (e < kth && h2[t] >= kth)
            s_T = (g_sel_b << 16) | ((unsigned int)t << 8);
    }
    __syncthreads();
    unsigned int T = s_T;

    // compact all keys >= T  (count <= kth-overshoot + sub-bucket size << CAP)
    const uint4* sp = (const uint4*)g_scores;
    for (int i = t; i < N_ANCH / 4; i += 1024) {
        uint4 k = sp[i];
        unsigned int bi = (unsigned int)(i * 4);
        if (k.x >= T) { int s = atomicAdd(&s_cnt, 1); if (s < CAP) cand[s] = ((unsigned long long)k.x << 32) | (0xFFFFFFFFu - bi); }
        if (k.y >= T) { int s = atomicAdd(&s_cnt, 1); if (s < CAP) cand[s] = ((unsigned long long)k.y << 32) | (0xFFFFFFFFu - (bi + 1)); }
        if (k.z >= T) { int s = atomicAdd(&s_cnt, 1); if (s < CAP) cand[s] = ((unsigned long long)k.z << 32) | (0xFFFFFFFFu - (bi + 2)); }
        if (k.w >= T) { int s = atomicAdd(&s_cnt, 1); if (s < CAP) cand[s] = ((unsigned long long)k.w << 32) | (0xFFFFFFFFu - (bi + 3)); }
    }
    __syncthreads();
    int cnt = s_cnt;
    if (cnt > CAP) cnt = CAP;
    int S = (cnt <= 2048) ? 2048 : CAP;
    for (int i = t; i < S; i += 1024)
        if (i >= cnt) cand[i] = 0ull;
    __syncthreads();

    // bitonic sort descending over S
    for (int k = 2; k <= S; k <<= 1) {
        for (int j = k >> 1; j > 0; j >>= 1) {
            for (int idx = t; idx < S; idx += 1024) {
                int l = idx ^ j;
                if (l > idx) {
                    bool up = ((idx & k) == 0);
                    unsigned long long a = cand[idx], b = cand[l];
                    bool sw = up ? (a < b) : (a > b);
                    if (sw) { cand[idx] = b; cand[l] = a; }
                }
            }
            __syncthreads();
        }
    }
    if (t < TOPK) {
        unsigned long long key = cand[t];
        int idx = (int)(0xFFFFFFFFu - (unsigned int)key);
        g_topk_idx[t] = idx;
        g_boxk[t] = ((const float4*)boxes)[idx];
    }
}

// ========== 5. IoU > thr bitmask matrix (bit-exact fp32, verified) ==========
__global__ void mask_kernel() {
    int w = blockIdx.x * blockDim.x + threadIdx.x;
    if (w >= TOPK * 32) return;
    int i = w >> 5, wj = w & 31;
    float4 bi = g_boxk[i];
    float ai = __fmul_rn(__fsub_rn(bi.z, bi.x), __fsub_rn(bi.w, bi.y));
    unsigned int bits = 0u;
    int j0 = wj * 32;
#pragma unroll 8
    for (int t = 0; t < 32; t++) {
        int j = j0 + t;
        if (j < TOPK) {
            float4 bj = g_boxk[j];
            float aj = __fmul_rn(__fsub_rn(bj.z, bj.x), __fsub_rn(bj.w, bj.y));
            float ih = fmaxf(__fsub_rn(fminf(bi.z, bj.z), fmaxf(bi.x, bj.x)), 0.0f);
            float iw = fmaxf(__fsub_rn(fminf(bi.w, bj.w), fmaxf(bi.y, bj.y)), 0.0f);
            float inter = __fmul_rn(ih, iw);
            float denom = __fadd_rn(__fsub_rn(__fadd_rn(ai, aj), inter), 1e-8f);
            float iou = __fdiv_rn(inter, denom);
            if (iou > NMS_THR) bits |= (1u << t);
        }
    }
    g_maskmat[w] = bits;
}

// ========== 6. sequential greedy keep-scan + output gather (verified) ==========
__global__ void scan_out_kernel(const float* __restrict__ det, float* __restrict__ out) {
    extern __shared__ unsigned int smask[];  // TOPK*32 words
    __shared__ unsigned int keepw[32];
    __shared__ unsigned int wpref[32];
    __shared__ int s_sel[MAXBOX];
    __shared__ int s_nkeep;
    int tid = threadIdx.x;
    for (int i = tid; i < TOPK * 32; i += blockDim.x) smask[i] = g_maskmat[i];
    __syncthreads();

    if (tid < 32) {
        unsigned int kw = 0u;
        for (int i = 0; i < TOPK; i++) {
            unsigned int m = smask[i * 32 + tid];
            int any = __any_sync(0xFFFFFFFFu, (kw & m) != 0u);
            if (!any && tid == (i >> 5)) kw |= 1u << (i & 31);
        }
        keepw[tid] = kw;
        unsigned int pc = __popc(kw);
        unsigned int inc = pc;
        for (int off = 1; off < 32; off <<= 1) {
            unsigned int v = __shfl_up_sync(0xFFFFFFFFu, inc, off);
            if (tid >= off) inc += v;
        }
        wpref[tid] = inc - pc;
        if (tid == 31) s_nkeep = (int)inc;
    }
    __syncthreads();

    if (tid < TOPK) {
        int w = tid >> 5, b = tid & 31;
        unsigned int kw = keepw[w];
        if ((kw >> b) & 1u) {
            int rank = (int)wpref[w] + __popc(kw & ((1u << b) - 1u));
            if (rank < MAXBOX) s_sel[rank] = g_topk_idx[tid];
        }
    }
    __syncthreads();

    int nk = s_nkeep;
    if (nk > MAXBOX) nk = MAXBOX;
    for (int e = tid; e < MAXBOX * DET_DIM; e += blockDim.x) {
        int r = e / DET_DIM;
        int c = e - r * DET_DIM;
        out[e] = (r < nk) ? det[(size_t)s_sel[r] * DET_DIM + c] : 0.0f;
    }
}

// ---------------- launch ----------------
extern "C" void kernel_launch(void* const* d_in, const int* in_sizes, int n_in,
                              void* d_out, int out_size) {
    const float* boxes = (const float*)d_in[0];
    const float* cls   = (const float*)d_in[1];
    const float* det   = (const float*)d_in[2];
    float* out = (float*)d_out;

    cudaFuncSetAttribute(scan_out_kernel,
                         cudaFuncAttributeMaxDynamicSharedMemorySize,
                         TOPK * 32 * sizeof(unsigned int));

    score_hist_kernel<<<AGRID, ATHREADS>>>(cls);
    resolve1_kernel<<<1, 1024>>>();
    hist2_kernel<<<(N_ANCH / 4 + 255) / 256, 256>>>();
    select_sort_kernel<<<1, 1024>>>(boxes);
    mask_kernel<<<(TOPK * 32 + 255) / 256, 256>>>();
    scan_out_kernel<<<1, 1024, TOPK * 32 * sizeof(unsigned int)>>>(det, out);
}

// round 3
// speedup vs baseline: 1.9912x; 1.9912x over previous
#include <cuda_runtime.h>
#include <cstdint>

#define N_ANCH   300000
#define N_CLS    80
#define DET_DIM  85
#define TOPK     1000
#define MAXBOX   300
#define CAP      4096
#define NMS_THR  0.4f

#define ABLK     80          // anchors per block in score kernel
#define ATHREADS 320
#define AGRID    (N_ANCH / ABLK)   // 3750

// ---------------- device scratch ----------------
__device__ unsigned int       g_scores[N_ANCH];
__device__ unsigned int       g_hist1[65536];   // bits [31:16]; zeroed by resolve1
__device__ unsigned int       g_hist2[256];     // bits [15:8]; zeroed by score kernel blk0
__device__ unsigned int       g_sel_b;
__device__ unsigned int       g_kth2;
__device__ unsigned int       g_T;              // final 24-bit-prefix threshold
__device__ int                g_cand_cnt;
__device__ unsigned long long g_cand[CAP];
__device__ int                g_topk_idx[TOPK];
__device__ float4             g_boxk[TOPK];
__device__ unsigned int       g_maskmat[TOPK * 32];

// ========== 1. coalesced per-anchor max (two-stage smem reduce) + 16-bit hist ==========
__global__ void score_hist_kernel(const float* __restrict__ cls) {
    __shared__ float sred[ABLK * (N_CLS / 4)];   // 1600 per-float4 maxima
    int t = threadIdx.x;
    if (blockIdx.x == 0 && t < 256) g_hist2[t] = 0u;

    const float4* p = (const float4*)cls;
    size_t base = (size_t)blockIdx.x * (ABLK * N_CLS / 4);
#pragma unroll
    for (int j = 0; j < 5; j++) {
        int off = t + j * ATHREADS;
        float4 v = p[base + off];
        sred[off] = fmaxf(fmaxf(v.x, v.y), fmaxf(v.z, v.w));
    }
    __syncthreads();

    if (t < ABLK) {
        const float* r = &sred[t * (N_CLS / 4)];
        float m = r[0];
#pragma unroll
        for (int i = 1; i < N_CLS / 4; i++) m = fmaxf(m, r[i]);
        unsigned int k = __float_as_uint(m);          // scores >= 0 -> monotonic bits
        g_scores[blockIdx.x * ABLK + t] = k;
        unsigned int bucket = k >> 16;
        unsigned int amask = __activemask();
        unsigned int peers = __match_any_sync(amask, bucket);
        int leader = __ffs(peers) - 1;
        if ((t & 31) == leader) atomicAdd(&g_hist1[bucket], __popc(peers));
    }
}

// ========== 2. resolve round 1: winning 16-bit bucket (+ zero hist1, reset counters) ==========
__global__ void resolve1_kernel() {
    __shared__ unsigned int suf[1024];
    __shared__ unsigned int win64[64];
    __shared__ int s_win;
    int t = threadIdx.x;   // 1024
    if (t == 0) g_cand_cnt = 0;

    unsigned int s = 0;
    const uint4* hp = (const uint4*)g_hist1;
#pragma unroll
    for (int i = 0; i < 16; i++) {
        uint4 v = hp[t * 16 + i];
        s += v.x + v.y + v.z + v.w;
    }
    suf[t] = s;
    __syncthreads();
    for (int off = 1; off < 1024; off <<= 1) {
        unsigned int v = suf[t];
        unsigned int u = (t + off < 1024) ? suf[t + off] : 0u;
        __syncthreads();
        suf[t] = v + u;
        __syncthreads();
    }
    unsigned int excl = (t < 1023) ? suf[t + 1] : 0u;
    if (excl < TOPK && suf[t] >= TOPK) s_win = t;
    __syncthreads();

    int w = s_win;
    unsigned int wexcl = (w < 1023) ? suf[w + 1] : 0u;
    if (t < 64) win64[t] = g_hist1[w * 64 + t];
    __syncthreads();
    for (int off = 1; off < 64; off <<= 1) {
        unsigned int v = 0, u = 0;
        if (t < 64) { v = win64[t]; u = (t + off < 64) ? win64[t + off] : 0u; }
        __syncthreads();
        if (t < 64) win64[t] = v + u;
        __syncthreads();
    }
    if (t < 64) {
        unsigned int e = wexcl + ((t < 63) ? win64[t + 1] : 0u);
        unsigned int inc = wexcl + win64[t];
        if (e < TOPK && inc >= TOPK) {
            g_sel_b = (unsigned int)(w * 64 + t);
            g_kth2  = TOPK - e;
        }
    }
    __syncthreads();
    uint4 z = make_uint4(0, 0, 0, 0);
    uint4* hz = (uint4*)g_hist1;
#pragma unroll
    for (int i = 0; i < 16; i++) hz[t * 16 + i] = z;
}

// ========== 3. 8-bit refinement histogram (grid-wide) ==========
__global__ void hist2_kernel() {
    __shared__ unsigned int sh[256];
    if (threadIdx.x < 256) sh[threadIdx.x] = 0u;
    __syncthreads();
    unsigned int b = g_sel_b;
    int i = blockIdx.x * blockDim.x + threadIdx.x;
    if (i < N_ANCH / 4) {
        uint4 k = ((const uint4*)g_scores)[i];
        if ((k.x >> 16) == b) atomicAdd(&sh[(k.x >> 8) & 255u], 1u);
        if ((k.y >> 16) == b) atomicAdd(&sh[(k.y >> 8) & 255u], 1u);
        if ((k.z >> 16) == b) atomicAdd(&sh[(k.z >> 8) & 255u], 1u);
        if ((k.w >> 16) == b) atomicAdd(&sh[(k.w >> 8) & 255u], 1u);
    }
    __syncthreads();
    if (threadIdx.x < 256 && sh[threadIdx.x])
        atomicAdd(&g_hist2[threadIdx.x], sh[threadIdx.x]);
}

// ========== 4. resolve2 (tiny, 1 block of 256) ==========
__global__ void resolve2_kernel() {
    __shared__ unsigned int h2[256];
    int t = threadIdx.x;   // 256
    h2[t] = g_hist2[t];
    __syncthreads();
    for (int off = 1; off < 256; off <<= 1) {
        unsigned int v = h2[t];
        unsigned int u = (t + off < 256) ? h2[t + off] : 0u;
        __syncthreads();
        h2[t] = v + u;
        __syncthreads();
    }
    unsigned int kth = g_kth2;
    unsigned int e = (t < 255) ? h2[t + 1] : 0u;
    if (e < kth && h2[t] >= kth)
        g_T = (g_sel_b << 16) | ((unsigned int)t << 8);
}

// ========== 5. grid-wide compact: keys >= T ==========
__global__ void compact_kernel() {
    unsigned int T = g_T;
    int i = blockIdx.x * blockDim.x + threadIdx.x;
    if (i >= N_ANCH / 4) return;
    uint4 k = ((const uint4*)g_scores)[i];
    unsigned int bi = (unsigned int)(i * 4);
    if (k.x >= T) { int s = atomicAdd(&g_cand_cnt, 1); if (s < CAP) g_cand[s] = ((unsigned long long)k.x << 32) | (0xFFFFFFFFu - bi); }
    if (k.y >= T) { int s = atomicAdd(&g_cand_cnt, 1); if (s < CAP) g_cand[s] = ((unsigned long long)k.y << 32) | (0xFFFFFFFFu - (bi + 1)); }
    if (k.z >= T) { int s = atomicAdd(&g_cand_cnt, 1); if (s < CAP) g_cand[s] = ((unsigned long long)k.z << 32) | (0xFFFFFFFFu - (bi + 2)); }
    if (k.w >= T) { int s = atomicAdd(&g_cand_cnt, 1); if (s < CAP) g_cand[s] = ((unsigned long long)k.w << 32) | (0xFFFFFFFFu - (bi + 3)); }
}

// ========== 6. single-block bitonic sort of candidates + box gather ==========
__global__ void sort_kernel(const float* __restrict__ boxes) {
    __shared__ unsigned long long s[CAP];
    int t = threadIdx.x;   // 1024
    int cnt = g_cand_cnt;
    if (cnt > CAP) cnt = CAP;
    int S = (cnt <= 2048) ? 2048 : CAP;
    for (int i = t; i < S; i += 1024)
        s[i] = (i < cnt) ? g_cand[i] : 0ull;
    __syncthreads();
    for (int k = 2; k <= S; k <<= 1) {
        for (int j = k >> 1; j > 0; j >>= 1) {
            for (int idx = t; idx < S; idx += 1024) {
                int l = idx ^ j;
                if (l > idx) {
                    bool up = ((idx & k) == 0);
                    unsigned long long a = s[idx], b = s[l];
                    bool sw = up ? (a < b) : (a > b);
                    if (sw) { s[idx] = b; s[l] = a; }
                }
            }
            __syncthreads();
        }
    }
    if (t < TOPK) {
        unsigned long long key = s[t];
        int idx = (int)(0xFFFFFFFFu - (unsigned int)key);
        g_topk_idx[t] = idx;
        g_boxk[t] = ((const float4*)boxes)[idx];
    }
}

// ========== 7. IoU > thr bitmask matrix (bit-exact fp32, verified) ==========
__global__ void mask_kernel() {
    int w = blockIdx.x * blockDim.x + threadIdx.x;
    if (w >= TOPK * 32) return;
    int i = w >> 5, wj = w & 31;
    float4 bi = g_boxk[i];
    float ai = __fmul_rn(__fsub_rn(bi.z, bi.x), __fsub_rn(bi.w, bi.y));
    unsigned int bits = 0u;
    int j0 = wj * 32;
#pragma unroll 8
    for (int t = 0; t < 32; t++) {
        int j = j0 + t;
        if (j < TOPK) {
            float4 bj = g_boxk[j];
            float aj = __fmul_rn(__fsub_rn(bj.z, bj.x), __fsub_rn(bj.w, bj.y));
            float ih = fmaxf(__fsub_rn(fminf(bi.z, bj.z), fmaxf(bi.x, bj.x)), 0.0f);
            float iw = fmaxf(__fsub_rn(fminf(bi.w, bj.w), fmaxf(bi.y, bj.y)), 0.0f);
            float inter = __fmul_rn(ih, iw);
            float denom = __fadd_rn(__fsub_rn(__fadd_rn(ai, aj), inter), 1e-8f);
            float iou = __fdiv_rn(inter, denom);
            if (iou > NMS_THR) bits |= (1u << t);
        }
    }
    g_maskmat[w] = bits;
}

// ========== 8. sequential greedy keep-scan + output gather ==========
__global__ void scan_out_kernel(const float* __restrict__ det, float* __restrict__ out) {
    extern __shared__ unsigned int smask[];  // TOPK*32 words
    __shared__ unsigned int keepw[32];
    __shared__ unsigned int wpref[32];
    __shared__ int s_sel[MAXBOX];
    __shared__ int s_nkeep;
    int tid = threadIdx.x;
    for (int i = tid; i < TOPK * 32; i += blockDim.x) smask[i] = g_maskmat[i];
    __syncthreads();

    if (tid < 32) {
        unsigned int kw = 0u;
        unsigned int m = smask[tid];          // prefetch i=0
        for (int i = 0; i < TOPK; i++) {
            unsigned int mn = (i + 1 < TOPK) ? smask[(i + 1) * 32 + tid] : 0u;
            int any = __any_sync(0xFFFFFFFFu, (kw & m) != 0u);
            if (!any && tid == (i >> 5)) kw |= 1u << (i & 31);
            m = mn;
        }
        keepw[tid] = kw;
        unsigned int pc = __popc(kw);
        unsigned int inc = pc;
        for (int off = 1; off < 32; off <<= 1) {
            unsigned int v = __shfl_up_sync(0xFFFFFFFFu, inc, off);
            if (tid >= off) inc += v;
        }
        wpref[tid] = inc - pc;
        if (tid == 31) s_nkeep = (int)inc;
    }
    __syncthreads();

    if (tid < TOPK) {
        int w = tid >> 5, b = tid & 31;
        unsigned int kw = keepw[w];
        if ((kw >> b) & 1u) {
            int rank = (int)wpref[w] + __popc(kw & ((1u << b) - 1u));
            if (rank < MAXBOX) s_sel[rank] = g_topk_idx[tid];
        }
    }
    __syncthreads();

    int nk = s_nkeep;
    if (nk > MAXBOX) nk = MAXBOX;
    for (int e = tid; e < MAXBOX * DET_DIM; e += blockDim.x) {
        int r = e / DET_DIM;
        int c = e - r * DET_DIM;
        out[e] = (r < nk) ? det[(size_t)s_sel[r] * DET_DIM + c] : 0.0f;
    }
}

// ---------------- launch ----------------
extern "C" void kernel_launch(void* const* d_in, const int* in_sizes, int n_in,
                              void* d_out, int out_size) {
    const float* boxes = (const float*)d_in[0];
    const float* cls   = (const float*)d_in[1];
    const float* det   = (const float*)d_in[2];
    float* out = (float*)d_out;

    cudaFuncSetAttribute(scan_out_kernel,
                         cudaFuncAttributeMaxDynamicSharedMemorySize,
                         TOPK * 32 * sizeof(unsigned int));

    score_hist_kernel<<<AGRID, ATHREADS>>>(cls);
    resolve1_kernel<<<1, 1024>>>();
    hist2_kernel<<<(N_ANCH / 4 + 255) / 256, 256>>>();
    resolve2_kernel<<<1, 256>>>();
    compact_kernel<<<(N_ANCH / 4 + 255) / 256, 256>>>();
    sort_kernel<<<1, 1024>>>(boxes);
    mask_kernel<<<(TOPK * 32 + 255) / 256, 256>>>();
    scan_out_kernel<<<1, 1024, TOPK * 32 * sizeof(unsigned int)>>>(det, out);
}